// round 14
// baseline (speedup 1.0000x reference)
#include <cuda_runtime.h>
#include <cuda_fp16.h>
#include <math.h>

#define B_   4096
#define T_   200
#define E_   64
#define H1_  80
#define H2_  40
#define NT   256

// strides (bytes): M rows = 144B (144%128=16 -> ldmatrix conflict-free)
//                  W2 rows = 176B (176%128=48 -> conflict-free)
#define KS  144
#define HS  176

// ---------------- smem layout (bytes) — no K tile anymore
#define OFF_M   0                       // [80][72]h   11520 (fp16, single)
#define OFF_W2  11520                   // [40][88]h    7040
#define OFF_C   18560                   // f32[80]
#define OFF_B2  18880                   // f32[40]
#define OFF_WD  19040                   // f32[40]
#define OFF_Q   19200                   // f32[64]
#define OFF_SC  19456                   // f32[224]
#define OFF_SP  20480                   // f32[8*64]
#define OFF_BD  22528
#define SMEM_TOTAL 22656                // x4 CTAs = 90.6KB smem -> huge L1D carveout

__device__ __forceinline__ unsigned smem_u32(const void* p) {
    unsigned a; asm("{ .reg .u64 t; cvta.to.shared.u64 t, %1; cvt.u32.u64 %0, t; }" : "=r"(a) : "l"(p));
    return a;
}
__device__ __forceinline__ void ldmx4(unsigned a[4], unsigned addr) {
    asm volatile("ldmatrix.sync.aligned.m8n8.x4.shared.b16 {%0,%1,%2,%3}, [%4];"
                 : "=r"(a[0]), "=r"(a[1]), "=r"(a[2]), "=r"(a[3]) : "r"(addr));
}
__device__ __forceinline__ void ldmx2(unsigned a[2], unsigned addr) {
    asm volatile("ldmatrix.sync.aligned.m8n8.x2.shared.b16 {%0,%1}, [%2];"
                 : "=r"(a[0]), "=r"(a[1]) : "r"(addr));
}
__device__ __forceinline__ void mma16816(float d[4], const unsigned a[4], const unsigned b[2]) {
    asm volatile("mma.sync.aligned.m16n8k16.row.col.f32.f16.f16.f32 "
                 "{%0,%1,%2,%3},{%4,%5,%6,%7},{%8,%9},{%0,%1,%2,%3};"
                 : "+f"(d[0]), "+f"(d[1]), "+f"(d[2]), "+f"(d[3])
                 : "r"(a[0]), "r"(a[1]), "r"(a[2]), "r"(a[3]), "r"(b[0]), "r"(b[1]));
}
// sigmoid(x) = 0.5*tanh(0.5x)+0.5 : FMUL + MUFU.TANH + FFMA
__device__ __forceinline__ float sigf(float x) {
    float t;
    asm("tanh.approx.f32 %0, %1;" : "=f"(t) : "f"(0.5f * x));
    return fmaf(0.5f, t, 0.5f);
}

// ---------------- device scratch
__device__ float    g_Wkt[H1_ * E_];   // (W1b - W1c)^T [h][e]
__device__ float    g_Wpt[H1_ * E_];   // W1d^T        [h][e]
__device__ float    g_Wqt[H1_ * E_];   // (W1a + W1c)^T[h][e]
__device__ unsigned g_W2h[1760];       // W2^T fp16 image [40 rows j][88 cols h], u32 words
__device__ int      g_len[B_];

// ---------------------------------------------------------------------------
__global__ void prep(const float* __restrict__ W1, const float* __restrict__ W2,
                     const int* __restrict__ raw) {
    int blk = blockIdx.x, tid = threadIdx.x;
    if (blk < 20) {                                   // W1 folds, transposed
        int idx = blk * 256 + tid;
        if (idx >= H1_ * E_) return;
        int h = idx >> 6, e = idx & 63;
        float wa = W1[(e         ) * H1_ + h];
        float wb = W1[(E_     + e) * H1_ + h];
        float wc = W1[(2 * E_ + e) * H1_ + h];
        float wd = W1[(3 * E_ + e) * H1_ + h];
        g_Wqt[idx] = wa + wc;
        g_Wkt[idx] = wb - wc;
        g_Wpt[idx] = wd;
    } else if (blk == 20) {                           // keys_length dtype sniff + clamp
        int any = 0;
        for (int i = 2 * tid + 1; i < B_; i += 512) any |= raw[i];
        int has_odd = __syncthreads_or(any);
        int is64 = (has_odd == 0);
        for (int i = tid; i < B_; i += 256) {
            int v = is64 ? raw[2 * i] : raw[i];
            g_len[i] = v < 0 ? 0 : (v > T_ ? T_ : v);
        }
    } else {                                          // W2^T fp16 image
        int idx = (blk - 21) * 256 + tid;
        if (idx < 1760) {
            int j = idx / 44, w = idx - j * 44;
            int h0 = 2 * w;
            float v0 = (h0     < H1_) ? W2[h0 * H2_ + j]       : 0.f;
            float v1 = (h0 + 1 < H1_) ? W2[(h0 + 1) * H2_ + j] : 0.f;
            __half2 p = __floats2half2_rn(v0, v1);
            g_W2h[idx] = *(unsigned*)&p;
        }
    }
}

// ---------------------------------------------------------------------------
extern __shared__ char smem[];

__global__ void __launch_bounds__(NT, 4)
din_mma(const float* __restrict__ query, const float* __restrict__ keys,
        const float* __restrict__ b1v,   const float* __restrict__ b2v,
        const float* __restrict__ Wdv,   const float* __restrict__ bdv,
        float* __restrict__ out)
{
    const int tid  = threadIdx.x;
    const int wid  = tid >> 5;
    const int lane = tid & 31;
    const int b    = blockIdx.x;
    const int len  = g_len[b];
    const unsigned sb = smem_u32(smem);

    // fragment lane constants
    const int g     = lane >> 2;
    const int t2    = (lane & 3) * 2;
    const int brow  = lane & 7;
    const int bcolB = ((lane >> 3) & 1) * 16;

    float* sQ  = (float*)(smem + OFF_Q);
    float* sC  = (float*)(smem + OFF_C);
    float* sB2 = (float*)(smem + OFF_B2);
    float* sWd = (float*)(smem + OFF_WD);
    float* sSc = (float*)(smem + OFF_SC);
    float* sSp = (float*)(smem + OFF_SP);

    // ---- phase 0: small vectors
    if (tid < E_) sQ[tid] = query[b * E_ + tid];
    if (tid >= 64 && tid < 64 + H2_) { int j = tid - 64; sB2[j] = b2v[j]; sWd[j] = Wdv[j]; }
    if (tid == 104) *(float*)(smem + OFF_BD) = bdv[0];
    __syncthreads();

    // ---- phase 1: M (single fp16), C, W2 copy — static trips, unrolled for MLP
    #pragma unroll 5
    for (int r = 0; r < (H1_ * E_) / NT; r++) {        // exactly 20 trips
        int idx = tid + r * NT;
        int h = idx >> 6, e = idx & 63;
        float v = g_Wkt[idx] + sQ[e] * g_Wpt[idx];
        *(__half*)(smem + OFF_M + h * KS + e * 2) = __float2half_rn(v);
    }
    if (tid < H1_) {
        const float4* wq = (const float4*)&g_Wqt[tid * E_];
        const float4* q4 = (const float4*)sQ;
        float c = b1v[tid];
        #pragma unroll
        for (int i = 0; i < 16; i++) {
            float4 w = wq[i], q = q4[i];
            c += w.x * q.x + w.y * q.y + w.z * q.z + w.w * q.w;
        }
        sC[tid] = c;
    }
    #pragma unroll
    for (int r = 0; r < 7; r++) {                      // 1760 = 6.875 * 256
        int i = tid + r * NT;
        if (i < 1760) ((unsigned*)(smem + OFF_W2))[i] = g_W2h[i];
    }
    __syncthreads();

    const float bd = *(float*)(smem + OFF_BD);
    const int mt = (len + 15) >> 4;        // m16 tiles (<=13)

    // combined ldmatrix.x4 bases:
    //  - M: lanes 0-15 -> even n-tile (rows +0), lanes 16-31 -> odd n-tile (rows +8)
    //  - W2: lanes 0-15 -> n-tile pair lo, lanes 16-31 -> pair hi
    const unsigned bComb = sb + OFF_M + ((lane & 16) ? 8u * KS : 0u)
                         + (unsigned)brow * KS + bcolB;
    const unsigned wComb = sb + OFF_W2 + ((lane & 16) ? 8u * HS : 0u)
                         + (unsigned)brow * HS + bcolB;
    const unsigned w4Base = sb + OFF_W2 + (unsigned)(4 * 8 + brow) * HS + bcolB;
    const float* kbase = keys + (size_t)b * (T_ * E_);

    // ---- fused layer1+layer2: warps process tiles independently, A direct from global
    for (int tl = wid; tl < mt; tl += 8) {
        // A fragments straight from global fp32 (identical __floats2half2_rn numerics)
        const int r0 = tl * 16 + g;
        const int r1 = r0 + 8;
        const bool v0 = r0 < len, v1 = r1 < len;
        const float* k0 = kbase + (size_t)r0 * E_ + t2;
        const float* k1 = k0 + 8 * E_;
        unsigned A[4][4];
        #pragma unroll
        for (int kt = 0; kt < 4; kt++) {
            int c0 = kt * 16;
            float2 x0 = v0 ? *(const float2*)(k0 + c0)     : make_float2(0.f, 0.f);
            float2 x1 = v1 ? *(const float2*)(k1 + c0)     : make_float2(0.f, 0.f);
            float2 x2 = v0 ? *(const float2*)(k0 + c0 + 8) : make_float2(0.f, 0.f);
            float2 x3 = v1 ? *(const float2*)(k1 + c0 + 8) : make_float2(0.f, 0.f);
            __half2 h0 = __floats2half2_rn(x0.x, x0.y);
            __half2 h1 = __floats2half2_rn(x1.x, x1.y);
            __half2 h2 = __floats2half2_rn(x2.x, x2.y);
            __half2 h3 = __floats2half2_rn(x3.x, x3.y);
            A[kt][0] = *(unsigned*)&h0; A[kt][1] = *(unsigned*)&h1;
            A[kt][2] = *(unsigned*)&h2; A[kt][3] = *(unsigned*)&h3;
        }

        float D2[5][4];
        #pragma unroll
        for (int n = 0; n < 5; n++) {          // fold b2 into init
            int j0 = n * 8 + t2;
            float bb0 = sB2[j0], bb1 = sB2[j0 + 1];
            D2[n][0] = bb0; D2[n][1] = bb1; D2[n][2] = bb0; D2[n][3] = bb1;
        }

        #pragma unroll
        for (int kc = 0; kc < 5; kc++) {       // k-chunk = n-tile pair (2kc, 2kc+1)
            float2 cA = *(float2*)&sC[kc * 16 + t2];
            float2 cB = *(float2*)&sC[kc * 16 + t2 + 8];
            float De[4] = {cA.x, cA.y, cA.x, cA.y};
            float Do[4] = {cB.x, cB.y, cB.x, cB.y};
            unsigned bB = bComb + (unsigned)(kc * 16) * KS;
            #pragma unroll
            for (int kt = 0; kt < 4; kt++) {
                unsigned B4[4];                // r0,r1 = even n-tile; r2,r3 = odd
                ldmx4(B4, bB + kt * 32);
                mma16816(De, A[kt], B4);
                mma16816(Do, A[kt], B4 + 2);
            }
            // epilogue -> A2 fragment (rows g/g+8, k16 chunk kc of layer-2)
            __half2 a0 = __floats2half2_rn(sigf(De[0]), sigf(De[1]));
            __half2 a1 = __floats2half2_rn(sigf(De[2]), sigf(De[3]));
            __half2 a2 = __floats2half2_rn(sigf(Do[0]), sigf(Do[1]));
            __half2 a3 = __floats2half2_rn(sigf(Do[2]), sigf(Do[3]));
            unsigned A2[4] = { *(unsigned*)&a0, *(unsigned*)&a1,
                               *(unsigned*)&a2, *(unsigned*)&a3 };
            unsigned Bw01[4], Bw23[4], Bw4[2];
            ldmx4(Bw01, wComb + (unsigned)(kc * 32));
            ldmx4(Bw23, wComb + 16u * HS + (unsigned)(kc * 32));
            ldmx2(Bw4,  w4Base + (unsigned)(kc * 32));
            mma16816(D2[0], A2, Bw01);
            mma16816(D2[1], A2, Bw01 + 2);
            mma16816(D2[2], A2, Bw23);
            mma16816(D2[3], A2, Bw23 + 2);
            mma16816(D2[4], A2, Bw4);
        }

        // ---- scores: sigmoid(D2) . Wd, reduce over n within lane quad
        float p0 = 0.f, p1 = 0.f;
        #pragma unroll
        for (int n = 0; n < 5; n++) {
            int j0 = n * 8 + t2;
            float w0 = sWd[j0], w1 = sWd[j0 + 1];
            p0 += sigf(D2[n][0]) * w0 + sigf(D2[n][1]) * w1;
            p1 += sigf(D2[n][2]) * w0 + sigf(D2[n][3]) * w1;
        }
        p0 += __shfl_xor_sync(0xFFFFFFFFu, p0, 1);
        p0 += __shfl_xor_sync(0xFFFFFFFFu, p0, 2);
        p1 += __shfl_xor_sync(0xFFFFFFFFu, p1, 1);
        p1 += __shfl_xor_sync(0xFFFFFFFFu, p1, 2);
        if ((lane & 3) == 0) {
            sSc[tl * 16 + g]     = p0 + bd;
            sSc[tl * 16 + g + 8] = p1 + bd;
        }
    }
    __syncthreads();

    // ---- pooling (cooperative, one pass): 2 rows per warp-iter, float4 per lane-half
    const int esub = (lane & 15) * 4;
    float ac0 = 0.f, ac1 = 0.f, ac2 = 0.f, ac3 = 0.f;
    {
        const int rofs = lane >> 4;            // 0 or 1
        #pragma unroll 4
        for (int t = 2 * wid; t < len; t += 16) {
            int row = t + rofs;
            if (row < len) {
                float sv = sSc[row];
                float4 kv = *(const float4*)(kbase + (size_t)row * E_ + esub);
                ac0 += sv * kv.x;
                ac1 += sv * kv.y;
                ac2 += sv * kv.z;
                ac3 += sv * kv.w;
            }
        }
    }

    // ---- final reduce across warps (combine row-parity halves first)
    ac0 += __shfl_down_sync(0xFFFFFFFFu, ac0, 16);
    ac1 += __shfl_down_sync(0xFFFFFFFFu, ac1, 16);
    ac2 += __shfl_down_sync(0xFFFFFFFFu, ac2, 16);
    ac3 += __shfl_down_sync(0xFFFFFFFFu, ac3, 16);
    if (lane < 16) {
        float4 v = make_float4(ac0, ac1, ac2, ac3);
        *(float4*)&sSp[wid * 64 + esub] = v;
    }
    __syncthreads();
    if (tid < E_) {
        float o = 0.f;
        #pragma unroll
        for (int w = 0; w < 8; w++) o += sSp[w * 64 + tid];
        out[b * E_ + tid] = o;
    }
}

// ---------------------------------------------------------------------------
extern "C" void kernel_launch(void* const* d_in, const int* in_sizes, int n_in,
                              void* d_out, int out_size) {
    const float* query = (const float*)d_in[0];
    const float* keys  = (const float*)d_in[1];
    const int*   klen  = (const int*)  d_in[2];
    const float* W1    = (const float*)d_in[3];
    const float* b1    = (const float*)d_in[4];
    const float* W2    = (const float*)d_in[5];
    const float* b2    = (const float*)d_in[6];
    const float* Wd    = (const float*)d_in[7];
    const float* bd    = (const float*)d_in[8];
    float* out = (float*)d_out;

    cudaFuncSetAttribute(din_mma, cudaFuncAttributeMaxDynamicSharedMemorySize, SMEM_TOTAL);

    prep<<<28, 256>>>(W1, W2, klen);
    din_mma<<<B_, NT, SMEM_TOTAL>>>(query, keys, b1, b2, Wd, bd, out);
}

// round 15
// speedup vs baseline: 1.0630x; 1.0630x over previous
#include <cuda_runtime.h>
#include <cuda_fp16.h>
#include <math.h>

#define B_   4096
#define T_   200
#define E_   64
#define H1_  80
#define H2_  40
#define NT   128
#define NW   4

// strides (bytes): M rows = 144B (144%128=16 -> ldmatrix conflict-free)
//                  W2 rows = 176B (176%128=48 -> conflict-free)
#define KS  144
#define HS  176

// ---------------- smem layout (bytes) — no K tile
#define OFF_M   0                       // [80][72]h   11520 (fp16, single)
#define OFF_W2  11520                   // [40][88]h    7040
#define OFF_C   18560                   // f32[80]
#define OFF_B2  18880                   // f32[40]
#define OFF_WD  19040                   // f32[40]
#define OFF_Q   19200                   // f32[64]
#define OFF_SC  19456                   // f32[224]
#define OFF_SP  20480                   // f32[4*64]
#define OFF_BD  22528
#define SMEM_TOTAL 22656                // x8 CTAs = 181KB <= 228KB/SM

__device__ __forceinline__ unsigned smem_u32(const void* p) {
    unsigned a; asm("{ .reg .u64 t; cvta.to.shared.u64 t, %1; cvt.u32.u64 %0, t; }" : "=r"(a) : "l"(p));
    return a;
}
__device__ __forceinline__ void ldmx4(unsigned a[4], unsigned addr) {
    asm volatile("ldmatrix.sync.aligned.m8n8.x4.shared.b16 {%0,%1,%2,%3}, [%4];"
                 : "=r"(a[0]), "=r"(a[1]), "=r"(a[2]), "=r"(a[3]) : "r"(addr));
}
__device__ __forceinline__ void ldmx2(unsigned a[2], unsigned addr) {
    asm volatile("ldmatrix.sync.aligned.m8n8.x2.shared.b16 {%0,%1}, [%2];"
                 : "=r"(a[0]), "=r"(a[1]) : "r"(addr));
}
__device__ __forceinline__ void mma16816(float d[4], const unsigned a[4], const unsigned b[2]) {
    asm volatile("mma.sync.aligned.m16n8k16.row.col.f32.f16.f16.f32 "
                 "{%0,%1,%2,%3},{%4,%5,%6,%7},{%8,%9},{%0,%1,%2,%3};"
                 : "+f"(d[0]), "+f"(d[1]), "+f"(d[2]), "+f"(d[3])
                 : "r"(a[0]), "r"(a[1]), "r"(a[2]), "r"(a[3]), "r"(b[0]), "r"(b[1]));
}
// sigmoid(x) = 0.5*tanh(0.5x)+0.5 : FMUL + MUFU.TANH + FFMA
__device__ __forceinline__ float sigf(float x) {
    float t;
    asm("tanh.approx.f32 %0, %1;" : "=f"(t) : "f"(0.5f * x));
    return fmaf(0.5f, t, 0.5f);
}

// ---------------- device scratch
__device__ float    g_Wkt[H1_ * E_];   // (W1b - W1c)^T [h][e]
__device__ float    g_Wpt[H1_ * E_];   // W1d^T        [h][e]
__device__ float    g_Wqt[H1_ * E_];   // (W1a + W1c)^T[h][e]
__device__ unsigned g_W2h[1760];       // W2^T fp16 image [40 rows j][88 cols h], u32 words
__device__ int      g_len[B_];

// ---------------------------------------------------------------------------
__global__ void prep(const float* __restrict__ W1, const float* __restrict__ W2,
                     const int* __restrict__ raw) {
    int blk = blockIdx.x, tid = threadIdx.x;
    if (blk < 20) {                                   // W1 folds, transposed
        int idx = blk * 256 + tid;
        if (idx >= H1_ * E_) return;
        int h = idx >> 6, e = idx & 63;
        float wa = W1[(e         ) * H1_ + h];
        float wb = W1[(E_     + e) * H1_ + h];
        float wc = W1[(2 * E_ + e) * H1_ + h];
        float wd = W1[(3 * E_ + e) * H1_ + h];
        g_Wqt[idx] = wa + wc;
        g_Wkt[idx] = wb - wc;
        g_Wpt[idx] = wd;
    } else if (blk == 20) {                           // keys_length dtype sniff + clamp
        int any = 0;
        for (int i = 2 * tid + 1; i < B_; i += 512) any |= raw[i];
        int has_odd = __syncthreads_or(any);
        int is64 = (has_odd == 0);
        for (int i = tid; i < B_; i += 256) {
            int v = is64 ? raw[2 * i] : raw[i];
            g_len[i] = v < 0 ? 0 : (v > T_ ? T_ : v);
        }
    } else {                                          // W2^T fp16 image
        int idx = (blk - 21) * 256 + tid;
        if (idx < 1760) {
            int j = idx / 44, w = idx - j * 44;
            int h0 = 2 * w;
            float v0 = (h0     < H1_) ? W2[h0 * H2_ + j]       : 0.f;
            float v1 = (h0 + 1 < H1_) ? W2[(h0 + 1) * H2_ + j] : 0.f;
            __half2 p = __floats2half2_rn(v0, v1);
            g_W2h[idx] = *(unsigned*)&p;
        }
    }
}

// ---------------------------------------------------------------------------
extern __shared__ char smem[];

__global__ void __launch_bounds__(NT, 8)
din_mma(const float* __restrict__ query, const float* __restrict__ keys,
        const float* __restrict__ b1v,   const float* __restrict__ b2v,
        const float* __restrict__ Wdv,   const float* __restrict__ bdv,
        float* __restrict__ out)
{
    const int tid  = threadIdx.x;
    const int wid  = tid >> 5;
    const int lane = tid & 31;
    const int b    = blockIdx.x;
    const int len  = g_len[b];
    const unsigned sb = smem_u32(smem);

    // fragment lane constants
    const int g     = lane >> 2;
    const int t2    = (lane & 3) * 2;
    const int brow  = lane & 7;
    const int bcolB = ((lane >> 3) & 1) * 16;

    float* sQ  = (float*)(smem + OFF_Q);
    float* sC  = (float*)(smem + OFF_C);
    float* sB2 = (float*)(smem + OFF_B2);
    float* sWd = (float*)(smem + OFF_WD);
    float* sSc = (float*)(smem + OFF_SC);
    float* sSp = (float*)(smem + OFF_SP);

    // ---- phase 0: small vectors
    if (tid < E_) sQ[tid] = query[b * E_ + tid];
    if (tid >= 64 && tid < 64 + H2_) { int j = tid - 64; sB2[j] = b2v[j]; sWd[j] = Wdv[j]; }
    if (tid == 104) *(float*)(smem + OFF_BD) = bdv[0];
    __syncthreads();

    // ---- phase 1: M (single fp16), C, W2 copy — static trips, unrolled for MLP
    #pragma unroll 5
    for (int r = 0; r < (H1_ * E_) / NT; r++) {        // exactly 40 trips
        int idx = tid + r * NT;
        int h = idx >> 6, e = idx & 63;
        float v = g_Wkt[idx] + sQ[e] * g_Wpt[idx];
        *(__half*)(smem + OFF_M + h * KS + e * 2) = __float2half_rn(v);
    }
    if (tid < H1_) {
        const float4* wq = (const float4*)&g_Wqt[tid * E_];
        const float4* q4 = (const float4*)sQ;
        float c = b1v[tid];
        #pragma unroll
        for (int i = 0; i < 16; i++) {
            float4 w = wq[i], q = q4[i];
            c += w.x * q.x + w.y * q.y + w.z * q.z + w.w * q.w;
        }
        sC[tid] = c;
    }
    #pragma unroll
    for (int r = 0; r < 14; r++) {                     // 1760 = 13.75 * 128
        int i = tid + r * NT;
        if (i < 1760) ((unsigned*)(smem + OFF_W2))[i] = g_W2h[i];
    }
    __syncthreads();

    const float bd = *(float*)(smem + OFF_BD);
    const int mt = (len + 15) >> 4;        // m16 tiles (<=13)

    // combined ldmatrix.x4 bases:
    //  - M: lanes 0-15 -> even n-tile (rows +0), lanes 16-31 -> odd n-tile (rows +8)
    //  - W2: lanes 0-15 -> n-tile pair lo, lanes 16-31 -> pair hi
    const unsigned bComb = sb + OFF_M + ((lane & 16) ? 8u * KS : 0u)
                         + (unsigned)brow * KS + bcolB;
    const unsigned wComb = sb + OFF_W2 + ((lane & 16) ? 8u * HS : 0u)
                         + (unsigned)brow * HS + bcolB;
    const unsigned w4Base = sb + OFF_W2 + (unsigned)(4 * 8 + brow) * HS + bcolB;
    const float* kbase = keys + (size_t)b * (T_ * E_);

    // ---- fused layer1+layer2: warps process tiles independently, A direct from global
    for (int tl = wid; tl < mt; tl += NW) {
        // A fragments straight from global fp32 (identical __floats2half2_rn numerics)
        const int r0 = tl * 16 + g;
        const int r1 = r0 + 8;
        const bool v0 = r0 < len, v1 = r1 < len;
        const float* k0 = kbase + (size_t)r0 * E_ + t2;
        const float* k1 = k0 + 8 * E_;
        unsigned A[4][4];
        #pragma unroll
        for (int kt = 0; kt < 4; kt++) {
            int c0 = kt * 16;
            float2 x0 = v0 ? *(const float2*)(k0 + c0)     : make_float2(0.f, 0.f);
            float2 x1 = v1 ? *(const float2*)(k1 + c0)     : make_float2(0.f, 0.f);
            float2 x2 = v0 ? *(const float2*)(k0 + c0 + 8) : make_float2(0.f, 0.f);
            float2 x3 = v1 ? *(const float2*)(k1 + c0 + 8) : make_float2(0.f, 0.f);
            __half2 h0 = __floats2half2_rn(x0.x, x0.y);
            __half2 h1 = __floats2half2_rn(x1.x, x1.y);
            __half2 h2 = __floats2half2_rn(x2.x, x2.y);
            __half2 h3 = __floats2half2_rn(x3.x, x3.y);
            A[kt][0] = *(unsigned*)&h0; A[kt][1] = *(unsigned*)&h1;
            A[kt][2] = *(unsigned*)&h2; A[kt][3] = *(unsigned*)&h3;
        }

        float D2[5][4];
        #pragma unroll
        for (int n = 0; n < 5; n++) {          // fold b2 into init
            int j0 = n * 8 + t2;
            float bb0 = sB2[j0], bb1 = sB2[j0 + 1];
            D2[n][0] = bb0; D2[n][1] = bb1; D2[n][2] = bb0; D2[n][3] = bb1;
        }

        #pragma unroll
        for (int kc = 0; kc < 5; kc++) {       // k-chunk = n-tile pair (2kc, 2kc+1)
            float2 cA = *(float2*)&sC[kc * 16 + t2];
            float2 cB = *(float2*)&sC[kc * 16 + t2 + 8];
            float De[4] = {cA.x, cA.y, cA.x, cA.y};
            float Do[4] = {cB.x, cB.y, cB.x, cB.y};
            unsigned bB = bComb + (unsigned)(kc * 16) * KS;
            #pragma unroll
            for (int kt = 0; kt < 4; kt++) {
                unsigned B4[4];                // r0,r1 = even n-tile; r2,r3 = odd
                ldmx4(B4, bB + kt * 32);
                mma16816(De, A[kt], B4);
                mma16816(Do, A[kt], B4 + 2);
            }
            // epilogue -> A2 fragment (rows g/g+8, k16 chunk kc of layer-2)
            __half2 a0 = __floats2half2_rn(sigf(De[0]), sigf(De[1]));
            __half2 a1 = __floats2half2_rn(sigf(De[2]), sigf(De[3]));
            __half2 a2 = __floats2half2_rn(sigf(Do[0]), sigf(Do[1]));
            __half2 a3 = __floats2half2_rn(sigf(Do[2]), sigf(Do[3]));
            unsigned A2[4] = { *(unsigned*)&a0, *(unsigned*)&a1,
                               *(unsigned*)&a2, *(unsigned*)&a3 };
            unsigned Bw01[4], Bw23[4], Bw4[2];
            ldmx4(Bw01, wComb + (unsigned)(kc * 32));
            ldmx4(Bw23, wComb + 16u * HS + (unsigned)(kc * 32));
            ldmx2(Bw4,  w4Base + (unsigned)(kc * 32));
            mma16816(D2[0], A2, Bw01);
            mma16816(D2[1], A2, Bw01 + 2);
            mma16816(D2[2], A2, Bw23);
            mma16816(D2[3], A2, Bw23 + 2);
            mma16816(D2[4], A2, Bw4);
        }

        // ---- scores: sigmoid(D2) . Wd, reduce over n within lane quad
        float p0 = 0.f, p1 = 0.f;
        #pragma unroll
        for (int n = 0; n < 5; n++) {
            int j0 = n * 8 + t2;
            float w0 = sWd[j0], w1 = sWd[j0 + 1];
            p0 += sigf(D2[n][0]) * w0 + sigf(D2[n][1]) * w1;
            p1 += sigf(D2[n][2]) * w0 + sigf(D2[n][3]) * w1;
        }
        p0 += __shfl_xor_sync(0xFFFFFFFFu, p0, 1);
        p0 += __shfl_xor_sync(0xFFFFFFFFu, p0, 2);
        p1 += __shfl_xor_sync(0xFFFFFFFFu, p1, 1);
        p1 += __shfl_xor_sync(0xFFFFFFFFu, p1, 2);
        if ((lane & 3) == 0) {
            sSc[tl * 16 + g]     = p0 + bd;
            sSc[tl * 16 + g + 8] = p1 + bd;
        }
    }
    __syncthreads();

    // ---- pooling (cooperative, one pass): 2 rows per warp-iter, float4 per lane-half
    const int esub = (lane & 15) * 4;
    float ac0 = 0.f, ac1 = 0.f, ac2 = 0.f, ac3 = 0.f;
    {
        const int rofs = lane >> 4;            // 0 or 1
        #pragma unroll 4
        for (int t = 2 * wid; t < len; t += 2 * NW) {
            int row = t + rofs;
            if (row < len) {
                float sv = sSc[row];
                float4 kv = *(const float4*)(kbase + (size_t)row * E_ + esub);
                ac0 += sv * kv.x;
                ac1 += sv * kv.y;
                ac2 += sv * kv.z;
                ac3 += sv * kv.w;
            }
        }
    }

    // ---- final reduce across warps (combine row-parity halves first)
    ac0 += __shfl_down_sync(0xFFFFFFFFu, ac0, 16);
    ac1 += __shfl_down_sync(0xFFFFFFFFu, ac1, 16);
    ac2 += __shfl_down_sync(0xFFFFFFFFu, ac2, 16);
    ac3 += __shfl_down_sync(0xFFFFFFFFu, ac3, 16);
    if (lane < 16) {
        float4 v = make_float4(ac0, ac1, ac2, ac3);
        *(float4*)&sSp[wid * 64 + esub] = v;
    }
    __syncthreads();
    if (tid < E_) {
        float o = 0.f;
        #pragma unroll
        for (int w = 0; w < NW; w++) o += sSp[w * 64 + tid];
        out[b * E_ + tid] = o;
    }
}

// ---------------------------------------------------------------------------
extern "C" void kernel_launch(void* const* d_in, const int* in_sizes, int n_in,
                              void* d_out, int out_size) {
    const float* query = (const float*)d_in[0];
    const float* keys  = (const float*)d_in[1];
    const int*   klen  = (const int*)  d_in[2];
    const float* W1    = (const float*)d_in[3];
    const float* b1    = (const float*)d_in[4];
    const float* W2    = (const float*)d_in[5];
    const float* b2    = (const float*)d_in[6];
    const float* Wd    = (const float*)d_in[7];
    const float* bd    = (const float*)d_in[8];
    float* out = (float*)d_out;

    cudaFuncSetAttribute(din_mma, cudaFuncAttributeMaxDynamicSharedMemorySize, SMEM_TOTAL);

    prep<<<28, 256>>>(W1, W2, klen);
    din_mma<<<B_, NT, SMEM_TOTAL>>>(query, keys, b1, b2, Wd, bd, out);
}